// round 8
// baseline (speedup 1.0000x reference)
#include <cuda_runtime.h>
#include <cstdint>
#include <cstddef>

#define NS   730
#define NG   1000
#define MUc  8
#define BATCH 4
#define PRECSf 1e-05f
#define XS   (NG*3)          // 3000 floats per timestep in x
#define PS   (NG*13*MUc)     // 104000 floats per timestep in parameters

__constant__ float LBc[13] = {1.0f, 50.0f, 0.05f, 0.01f, 0.001f, 0.2f, 0.0f, 0.0f, -2.5f, 0.5f, 0.0f, 0.0f, 0.3f};
__constant__ float UBc[13] = {6.0f, 1000.0f, 0.9f, 0.5f, 0.2f, 1.0f, 10.0f, 100.0f, 2.5f, 10.0f, 0.1f, 0.2f, 5.0f};

__device__ __forceinline__ float fast_lg2(float a) {
    float r; asm("lg2.approx.f32 %0, %1;" : "=f"(r) : "f"(a)); return r;
}
__device__ __forceinline__ float fast_ex2(float a) {
    float r; asm("ex2.approx.f32 %0, %1;" : "=f"(r) : "f"(a)); return r;
}

struct HState { float SP, MW, SM, SUZ, SLZ; };
struct HConst {
    float FC, K0, K1, K2, PERCc, UZL, TT, CWH;
    float CFMAX, negCFMAXTT, negCFR;
    float lgFC, neglgLPFC;
};

__device__ __forceinline__ HConst make_const(const float* __restrict__ pb) {
    float cp[13];
    #pragma unroll
    for (int p = 0; p < 13; p++)
        cp[p] = fmaf(pb[p*MUc], (UBc[p]-LBc[p]), LBc[p]);
    HConst c;
    c.FC = cp[1]; c.K0 = cp[2]; c.K1 = cp[3]; c.K2 = cp[4];
    c.PERCc = cp[6]; c.UZL = cp[7]; c.TT = cp[8]; c.CWH = cp[11];
    c.CFMAX = cp[9];
    c.negCFMAXTT = -cp[9]*cp[8];
    c.negCFR = -cp[10];
    c.lgFC = fast_lg2(cp[1]);
    c.neglgLPFC = -fast_lg2(cp[5]*cp[1]);
    return c;
}

// one HBV step for one chain; lgE precomputed (shared between the two chains)
__device__ __forceinline__ float hbv_step(HState& s, const HConst& c,
    float P_, float T_, float E_, float BETAET, float BETA, float lgE)
{
    float m0 = fmaf(c.CFMAX, T_, c.negCFMAXTT);      // CFMAX*(T-TT)
    float mm = fmaxf(m0, 0.0f);
    float rr = fmaxf(c.negCFR*m0, 0.0f);             // max(CFR*CFMAX*(TT-T),0)
    bool  wet = (T_ >= c.TT);
    float rain = wet ? P_ : 0.0f;
    float snow = wet ? 0.0f : P_;
    float C1 = -BETA*c.lgFC;
    float C2 = fmaf(BETAET, c.neglgLPFC, lgE);
    // snow module
    s.SP += snow;
    float melt = fminf(mm, s.SP);
    s.MW += melt; s.SP -= melt;
    float refr = fminf(rr, s.MW);
    s.SP += refr; s.MW -= refr;
    float tosoil = fmaxf(fmaf(-c.CWH, s.SP, s.MW), 0.0f);
    s.MW -= tosoil;
    float rt = rain + tosoil;
    // soil module — the loop-carried critical chain
    float lgSM = fast_lg2(s.SM);
    float sw   = fast_ex2(fminf(fmaf(BETA, lgSM, C1), 0.0f));  // clip((SM/FC)^BETA,0,1)
    float recharge = rt * sw;
    float SM1 = (s.SM + rt) - recharge;
    float SM2 = fminf(SM1, c.FC);
    float excess = SM1 - SM2;
    float lgSM2 = fast_lg2(SM2);
    float ea    = fast_ex2(fmaf(BETAET, lgSM2, C2));   // E*(SM2/(LP*FC))^BETAET
    float ETact = fminf(fminf(SM2, E_), ea);
    s.SM = fmaxf(SM2 - ETact, PRECSf);
    // routing
    s.SUZ += recharge + excess;
    float PERC = fminf(s.SUZ, c.PERCc);
    s.SUZ -= PERC;
    float Q0 = c.K0 * fmaxf(s.SUZ - c.UZL, 0.0f);
    s.SUZ -= Q0;
    float Q1 = c.K1 * s.SUZ;
    s.SUZ -= Q1;
    s.SLZ += PERC;
    float Q2 = c.K2 * s.SLZ;
    s.SLZ -= Q2;
    return Q0 + Q1 + Q2;
}

// ============================================================================
// Specialized path: time-varying slots are exactly {12=BETAET, 0=BETA}.
// Each thread runs TWO chains: mu = mp and mu = mp+4 (mp = lane & 3).
// ============================================================================
__device__ __forceinline__ void run_spec(
    const float* __restrict__ x, const float* __restrict__ par,
    float* __restrict__ out, int g, int mp, int staind)
{
    const float* base = par + ((size_t)staind*NG + (size_t)g)*13u*MUc;
    HConst cA = make_const(base + mp);
    HConst cB = make_const(base + mp + 4);
    HState sA = {0.001f, 0.001f, 0.001f, 0.001f, 0.001f};
    HState sB = {0.001f, 0.001f, 0.001f, 0.001f, 0.001f};

    const float dBET = UBc[12]-LBc[12], lbBET = LBc[12];
    const float dB   = UBc[0] -LBc[0],  lbB   = LBc[0];
    const unsigned FULL = 0xffffffffu;
    const bool h2 = (mp & 2) != 0, h1 = (mp & 1) != 0;

    // streaming pointers: x row; BETA raw (slot 0); BETAET raw (slot 12).
    const float* xp  = x + g*3;
    const float* pB  = par + (size_t)g*13*MUc + 0*MUc  + mp;  // [+0]=muA, [+4]=muB
    const float* pBT = par + (size_t)g*13*MUc + 12*MUc + mp;
    float* outp = out + (size_t)mp*NG + g;   // step b*4+mp -> outp + b*4*NG

    // current-batch buffers (7 loads/step: 3 shared x + 4 params)
    float uP[BATCH], uT[BATCH], uE[BATCH];
    float a0[BATCH], a1[BATCH], b0[BATCH], b1[BATCH];  // a=BETAraw, b... a0/b0=BETA A/B, a1/b1=BETAET A/B
    #pragma unroll
    for (int j = 0; j < BATCH; j++) {
        uP[j] = xp[j*XS + 0];
        uT[j] = xp[j*XS + 1];
        uE[j] = xp[j*XS + 2];
        a0[j] = pB [j*PS + 0];
        b0[j] = pB [j*PS + 4];
        a1[j] = pBT[j*PS + 0];
        b1[j] = pBT[j*PS + 4];
    }

    // 182 full batches of 4 (steps 0..727); prefetch b+1 while computing b.
    for (int b = 0; b < 182; b++) {
        const bool pf = (b < 181);
        float nP[BATCH], nT[BATCH], nE[BATCH], na0[BATCH], na1[BATCH], nb0[BATCH], nb1[BATCH];
        if (pf) {
            const float* xq = xp  + BATCH*XS;
            const float* qB = pB  + BATCH*PS;
            const float* qT = pBT + BATCH*PS;
            #pragma unroll
            for (int j = 0; j < BATCH; j++) {
                nP[j]  = xq[j*XS + 0];
                nT[j]  = xq[j*XS + 1];
                nE[j]  = xq[j*XS + 2];
                na0[j] = qB[j*PS + 0];
                nb0[j] = qB[j*PS + 4];
                na1[j] = qT[j*PS + 0];
                nb1[j] = qT[j*PS + 4];
            }
        }
        // compute 4 steps, two independent chains per step (ILP=2)
        float q[BATCH];
        #pragma unroll
        for (int j = 0; j < BATCH; j++) {
            float lgE = fast_lg2(uE[j]);                     // shared MUFU
            float BA  = fmaf(a0[j], dB,   lbB);
            float BTA = fmaf(a1[j], dBET, lbBET);
            float BB  = fmaf(b0[j], dB,   lbB);
            float BTB = fmaf(b1[j], dBET, lbBET);
            float qa = hbv_step(sA, cA, uP[j], uT[j], uE[j], BTA, BA, lgE);
            float qb = hbv_step(sB, cB, uP[j], uT[j], uE[j], BTB, BB, lgE);
            q[j] = qa + qb;
        }
        // reduce-scatter over the 4-lane mu group: lane mp owns step b*4+mp
        float s1[2];
        #pragma unroll
        for (int e = 0; e < 2; e++) {
            float send = h2 ? q[e] : q[e+2];
            float recv = __shfl_xor_sync(FULL, send, 2);
            s1[e] = (h2 ? q[e+2] : q[e]) + recv;
        }
        {
            float send = h1 ? s1[0] : s1[1];
            float recv = __shfl_xor_sync(FULL, send, 1);
            float tot  = (h1 ? s1[1] : s1[0]) + recv;
            outp[0] = tot * 0.125f;
        }
        outp += BATCH*NG;
        if (pf) {
            xp += BATCH*XS;  pB += BATCH*PS;  pBT += BATCH*PS;
            #pragma unroll
            for (int j = 0; j < BATCH; j++) {
                uP[j]=nP[j]; uT[j]=nT[j]; uE[j]=nE[j];
                a0[j]=na0[j]; a1[j]=na1[j]; b0[j]=nb0[j]; b1[j]=nb1[j];
            }
        }
    }

    // tail: steps 728, 729
    const float* xt  = x + g*3;
    const float* tB  = par + (size_t)g*13*MUc + 0*MUc  + mp;
    const float* tBT = par + (size_t)g*13*MUc + 12*MUc + mp;
    #pragma unroll
    for (int t = 182*BATCH; t < NS; t++) {
        float P_ = xt[(long)t*XS + 0];
        float T_ = xt[(long)t*XS + 1];
        float E_ = xt[(long)t*XS + 2];
        float lgE = fast_lg2(E_);
        float BA  = fmaf(tB [(long)t*PS + 0], dB,   lbB);
        float BB  = fmaf(tB [(long)t*PS + 4], dB,   lbB);
        float BTA = fmaf(tBT[(long)t*PS + 0], dBET, lbBET);
        float BTB = fmaf(tBT[(long)t*PS + 4], dBET, lbBET);
        float qv = hbv_step(sA, cA, P_, T_, E_, BTA, BA, lgE)
                 + hbv_step(sB, cB, P_, T_, E_, BTB, BB, lgE);
        qv += __shfl_xor_sync(FULL, qv, 1);
        qv += __shfl_xor_sync(FULL, qv, 2);
        if (mp == 0) out[(size_t)t*NG + g] = qv * 0.125f;
    }
}

// ============================================================================
// Generic fallback (any i0/i1), dual-chain mapping, unoptimized but correct.
// ============================================================================
__device__ __forceinline__ void run_generic(
    const float* __restrict__ x, const float* __restrict__ par,
    float* __restrict__ out, int g, int mp, int staind, int i0, int i1)
{
    const unsigned FULL = 0xffffffffu;
    float cpA[13], cpB[13];
    {
        const float* pb = par + ((size_t)staind*NG + (size_t)g)*13u*MUc;
        #pragma unroll
        for (int p = 0; p < 13; p++) {
            cpA[p] = fmaf(pb[p*MUc + mp],     (UBc[p]-LBc[p]), LBc[p]);
            cpB[p] = fmaf(pb[p*MUc + mp + 4], (UBc[p]-LBc[p]), LBc[p]);
        }
    }
    const float lb0 = LBc[i0], d0 = UBc[i0]-LBc[i0];
    const float lb1 = LBc[i1], d1 = UBc[i1]-LBc[i1];
    const float* xp  = x   + (size_t)g*3;
    const float* pp0 = par + ((size_t)g*13 + (size_t)i0)*MUc + mp;
    const float* pp1 = par + ((size_t)g*13 + (size_t)i1)*MUc + mp;

    float SPa=0.001f, MWa=0.001f, SMa=0.001f, SUZa=0.001f, SLZa=0.001f;
    float SPb=0.001f, MWb=0.001f, SMb=0.001f, SUZb=0.001f, SLZb=0.001f;

    for (int t = 0; t < NS; t++) {
        float P_ = xp[(long)t*XS + 0];
        float T_ = xp[(long)t*XS + 1];
        float E_ = xp[(long)t*XS + 2];
        float qv = 0.0f;
        #pragma unroll
        for (int h = 0; h < 2; h++) {
            const float* cp = h ? cpB : cpA;
            float v0 = fmaf(pp0[(long)t*PS + h*4], d0, lb0);
            float v1 = fmaf(pp1[(long)t*PS + h*4], d1, lb1);
            float pr[13];
            #pragma unroll
            for (int p = 0; p < 13; p++) {
                float v = cp[p];
                if (p == i0) v = v0;
                if (p == i1) v = v1;
                pr[p] = v;
            }
            float BETA=pr[0], FC=pr[1], K0=pr[2], K1=pr[3], K2=pr[4], LP=pr[5],
                  PERCc=pr[6], UZL=pr[7], TT=pr[8], CFMAX=pr[9], CFR=pr[10],
                  CWH=pr[11], BETAET=pr[12];
            float& SP = h ? SPb : SPa;   float& MW = h ? MWb : MWa;
            float& SM = h ? SMb : SMa;   float& SUZ = h ? SUZb : SUZa;
            float& SLZ = h ? SLZb : SLZa;
            float rain = (T_ >= TT) ? P_ : 0.0f;
            float snow = P_ - rain;
            SP += snow;
            float melt = fminf(fmaxf(CFMAX*(T_-TT), 0.0f), SP);
            MW += melt; SP -= melt;
            float refr = fminf(fmaxf(CFR*CFMAX*(TT-T_), 0.0f), MW);
            SP += refr; MW -= refr;
            float tosoil = fmaxf(MW - CWH*SP, 0.0f);
            MW -= tosoil;
            float sw = fminf(fast_ex2(BETA*(fast_lg2(SM) - fast_lg2(FC))), 1.0f);
            float rt = rain + tosoil;
            float recharge = rt * sw;
            float SM1 = SM + rt - recharge;
            float excess = fmaxf(SM1 - FC, 0.0f);
            float SM2 = SM1 - excess;
            float ef = fminf(fast_ex2(BETAET*(fast_lg2(SM2) - fast_lg2(LP*FC))), 1.0f);
            float ETact = fminf(SM2, E_*ef);
            SM = fmaxf(SM2 - ETact, PRECSf);
            SUZ += recharge + excess;
            float PERC = fminf(SUZ, PERCc);
            SUZ -= PERC;
            float Q0 = K0 * fmaxf(SUZ - UZL, 0.0f);
            SUZ -= Q0;
            float Q1 = K1 * SUZ;
            SUZ -= Q1;
            SLZ += PERC;
            float Q2 = K2 * SLZ;
            SLZ -= Q2;
            qv += Q0 + Q1 + Q2;
        }
        qv += __shfl_xor_sync(FULL, qv, 1);
        qv += __shfl_xor_sync(FULL, qv, 2);
        if (mp == 0) out[(size_t)t*NG + g] = qv * 0.125f;
    }
}

__global__ void __launch_bounds__(32, 1)
hbv_kernel(const float* __restrict__ x, const float* __restrict__ par,
           const int* __restrict__ staind_p, const int* __restrict__ tdlst_p,
           int n_td, float* __restrict__ out)
{
    int tid = blockIdx.x * 32 + threadIdx.x;   // 4000 threads exactly
    int g  = tid >> 2;    // 0..999
    int mp = tid & 3;     // handles mu = mp and mu = mp+4
    int staind = staind_p[0];
    int t0 = tdlst_p[0];
    int t1 = (n_td > 1) ? tdlst_p[1] : t0;
    int i0 = ((t0 - 1) % 13 + 13) % 13;
    int i1 = ((t1 - 1) % 13 + 13) % 13;

    if ((i0 == 12 && i1 == 0) || (i0 == 0 && i1 == 12)) {
        run_spec(x, par, out, g, mp, staind);
    } else {
        run_generic(x, par, out, g, mp, staind, i0, i1);
    }
}

extern "C" void kernel_launch(void* const* d_in, const int* in_sizes, int n_in,
                              void* d_out, int out_size)
{
    const float* x      = (const float*)d_in[0];   // (730, 1000, 3) f32
    const float* par    = (const float*)d_in[1];   // (730, 1000, 13, 8) f32
    const int*   staind = (const int*)d_in[2];     // scalar
    const int*   tdlst  = (const int*)d_in[3];     // (2,) int32
    int n_td = in_sizes[3];
    (void)n_in; (void)out_size;
    hbv_kernel<<<125, 32>>>(x, par, staind, tdlst, n_td, (float*)d_out);
}

// round 11
// speedup vs baseline: 1.3933x; 1.3933x over previous
#include <cuda_runtime.h>
#include <cstdint>
#include <cstddef>

#define NS     730
#define NG     1000
#define MUc    8
#define NCHAIN 8000
#define TCHUNK 183          // ceil(732/4): 183 chunks of 4 steps (pad to 732)
#define PRECSf 1e-05f
#define XS     (NG*3)
#define PS     (NG*13*MUc)

__constant__ float LBc[13] = {1.0f, 50.0f, 0.05f, 0.01f, 0.001f, 0.2f, 0.0f, 0.0f, -2.5f, 0.5f, 0.0f, 0.0f, 0.3f};
__constant__ float UBc[13] = {6.0f, 1000.0f, 0.9f, 0.5f, 0.2f, 1.0f, 10.0f, 100.0f, 2.5f, 10.0f, 0.1f, 0.2f, 5.0f};

// Scratch (static device globals; zero-initialized once at module load).
// g_B/g_BT: [t4][chain] float4 = transformed BETA / BETAET for steps t4*4..+3.
// g_PTEL:   [t][g]     float4 = (P, T, E, lg2(E)); t=730,731 stay zero.
__device__ float4 g_B   [TCHUNK * NCHAIN];
__device__ float4 g_BT  [TCHUNK * NCHAIN];
__device__ float4 g_PTEL[732 * NG];

__device__ __forceinline__ float fast_lg2(float a) {
    float r; asm("lg2.approx.f32 %0, %1;" : "=f"(r) : "f"(a)); return r;
}
__device__ __forceinline__ float fast_ex2(float a) {
    float r; asm("ex2.approx.f32 %0, %1;" : "=f"(r) : "f"(a)); return r;
}

// ============================================================================
// Repack kernels
// ============================================================================
__global__ void __launch_bounds__(256) repack_par(const float* __restrict__ par)
{
    int id = blockIdx.x * 256 + threadIdx.x;       // id = t4*NCHAIN + c
    if (id >= TCHUNK * NCHAIN) return;
    int t4 = id / NCHAIN;
    int c  = id - t4 * NCHAIN;
    int g = c >> 3, m = c & 7;
    const float dB  = UBc[0]  - LBc[0],  lbB  = LBc[0];
    const float dBT = UBc[12] - LBc[12], lbBT = LBc[12];
    float4 vb, vbt;
    float* pb  = (float*)&vb;
    float* pbt = (float*)&vbt;
    #pragma unroll
    for (int k = 0; k < 4; k++) {
        int t = t4 * 4 + k;
        float rB = 0.0f, rBT = 0.0f;
        if (t < NS) {
            size_t base = ((size_t)t * NG + g) * (13u * MUc) + m;
            rB  = par[base + 0*MUc];
            rBT = par[base + 12*MUc];
        }
        pb [k] = fmaf(rB,  dB,  lbB);
        pbt[k] = fmaf(rBT, dBT, lbBT);
    }
    g_B [id] = vb;
    g_BT[id] = vbt;
}

__global__ void __launch_bounds__(256) repack_x(const float* __restrict__ x)
{
    int id = blockIdx.x * 256 + threadIdx.x;       // id = t*NG + g
    if (id >= NS * NG) return;
    float P = x[(size_t)id*3 + 0];
    float T = x[(size_t)id*3 + 1];
    float E = x[(size_t)id*3 + 2];
    g_PTEL[id] = make_float4(P, T, E, fast_lg2(E));
}

// ============================================================================
// Main kernel
// ============================================================================
struct HC {
    float FC, K0, K1, K2, PERCc, UZL, TT, negCWH;
    float CFMAX, negCFMAXTT, negCFR;
    float neglgFC, neglgLPFC;
};

__device__ __forceinline__ float hbv_step(
    float& SP, float& MW, float& SM, float& SUZ, float& SLZ, const HC& c,
    float P_, float T_, float E_, float lgE, float BETA, float BETAET)
{
    float m0 = fmaf(c.CFMAX, T_, c.negCFMAXTT);      // CFMAX*(T-TT)
    float mm = fmaxf(m0, 0.0f);
    float rr = fmaxf(c.negCFR * m0, 0.0f);
    bool  wet = (T_ >= c.TT);
    float rain = wet ? P_ : 0.0f;
    float snow = wet ? 0.0f : P_;
    float C1 = BETA   * c.neglgFC;
    float C2 = fmaf(BETAET, c.neglgLPFC, lgE);
    // snow module (off critical chain)
    SP += snow;
    float melt = fminf(mm, SP);
    MW += melt; SP -= melt;
    float refr = fminf(rr, MW);
    SP += refr; MW -= refr;
    float tosoil = fmaxf(fmaf(c.negCWH, SP, MW), 0.0f);
    MW -= tosoil;
    float rt = rain + tosoil;
    // soil module — loop-carried critical chain
    float lgSM = fast_lg2(SM);
    float sw   = fast_ex2(fminf(fmaf(BETA, lgSM, C1), 0.0f));   // clip((SM/FC)^BETA,0,1)
    float recharge = rt * sw;
    float SM1 = (SM + rt) - recharge;
    float SM2 = fminf(SM1, c.FC);
    float excess = SM1 - SM2;
    float lgSM2 = fast_lg2(SM2);
    float ea    = fast_ex2(fmaf(BETAET, lgSM2, C2));   // E*(SM2/(LP*FC))^BETAET
    float ETact = fminf(fminf(SM2, E_), ea);
    SM = fmaxf(SM2 - ETact, PRECSf);
    // routing
    SUZ += recharge + excess;
    float PERC = fminf(SUZ, c.PERCc);
    SUZ -= PERC;
    float Q0 = c.K0 * fmaxf(SUZ - c.UZL, 0.0f);
    SUZ -= Q0;
    float Q1 = c.K1 * SUZ;
    SUZ -= Q1;
    SLZ += PERC;
    float Q2 = c.K2 * SLZ;
    SLZ -= Q2;
    return Q0 + Q1 + Q2;
}

// Generic fallback (any i0/i1) — correctness-only path.
__device__ void run_generic(
    const float* __restrict__ x, const float* __restrict__ par,
    float* __restrict__ out, int g, int m, int staind, int i0, int i1)
{
    float cp[13];
    {
        const float* pb = par + ((size_t)staind*NG + (size_t)g)*13u*MUc + m;
        #pragma unroll
        for (int p = 0; p < 13; p++)
            cp[p] = fmaf(pb[p*MUc], (UBc[p]-LBc[p]), LBc[p]);
    }
    const float lb0 = LBc[i0], d0 = UBc[i0]-LBc[i0];
    const float lb1 = LBc[i1], d1 = UBc[i1]-LBc[i1];
    const float* xp  = x   + (size_t)g*3;
    const float* pp0 = par + ((size_t)g*13 + (size_t)i0)*MUc + m;
    const float* pp1 = par + ((size_t)g*13 + (size_t)i1)*MUc + m;

    float SP=0.001f, MW=0.001f, SM=0.001f, SUZ=0.001f, SLZ=0.001f;
    const unsigned FULL = 0xffffffffu;

    for (int t = 0; t < NS; t++) {
        float P_ = xp[(long)t*XS + 0];
        float T_ = xp[(long)t*XS + 1];
        float E_ = xp[(long)t*XS + 2];
        float v0 = fmaf(pp0[(long)t*PS], d0, lb0);
        float v1 = fmaf(pp1[(long)t*PS], d1, lb1);
        float pr[13];
        #pragma unroll
        for (int p = 0; p < 13; p++) {
            float v = cp[p];
            if (p == i0) v = v0;
            if (p == i1) v = v1;
            pr[p] = v;
        }
        float BETA=pr[0], FC=pr[1], K0=pr[2], K1=pr[3], K2=pr[4], LP=pr[5],
              PERCc=pr[6], UZL=pr[7], TT=pr[8], CFMAX=pr[9], CFR=pr[10],
              CWH=pr[11], BETAET=pr[12];
        float rain = (T_ >= TT) ? P_ : 0.0f;
        float snow = P_ - rain;
        SP += snow;
        float melt = fminf(fmaxf(CFMAX*(T_-TT), 0.0f), SP);
        MW += melt; SP -= melt;
        float refr = fminf(fmaxf(CFR*CFMAX*(TT-T_), 0.0f), MW);
        SP += refr; MW -= refr;
        float tosoil = fmaxf(MW - CWH*SP, 0.0f);
        MW -= tosoil;
        float sw = fminf(fast_ex2(BETA*(fast_lg2(SM) - fast_lg2(FC))), 1.0f);
        float rt = rain + tosoil;
        float recharge = rt * sw;
        float SM1 = SM + rt - recharge;
        float excess = fmaxf(SM1 - FC, 0.0f);
        float SM2 = SM1 - excess;
        float ef = fminf(fast_ex2(BETAET*(fast_lg2(SM2) - fast_lg2(LP*FC))), 1.0f);
        float ETact = fminf(SM2, E_*ef);
        SM = fmaxf(SM2 - ETact, PRECSf);
        SUZ += recharge + excess;
        float PERC = fminf(SUZ, PERCc);
        SUZ -= PERC;
        float Q0 = K0 * fmaxf(SUZ - UZL, 0.0f);
        SUZ -= Q0;
        float Q1 = K1 * SUZ;
        SUZ -= Q1;
        SLZ += PERC;
        float Q2 = K2 * SLZ;
        SLZ -= Q2;
        float qv = Q0 + Q1 + Q2;
        qv += __shfl_xor_sync(FULL, qv, 1);
        qv += __shfl_xor_sync(FULL, qv, 2);
        qv += __shfl_xor_sync(FULL, qv, 4);
        if (m == 0) out[(size_t)t*NG + g] = qv * 0.125f;
    }
}

__global__ void __launch_bounds__(256, 1)
hbv_main(const float* __restrict__ x, const float* __restrict__ par,
         const int* __restrict__ staind_p, const int* __restrict__ tdlst_p,
         int n_td, float* __restrict__ out)
{
    int tid = blockIdx.x * 256 + threadIdx.x;
    if (tid >= NCHAIN) return;        // whole trailing warps exit
    int g = tid >> 3, m = tid & 7;
    int staind = staind_p[0];
    int t0 = tdlst_p[0];
    int t1 = (n_td > 1) ? tdlst_p[1] : t0;
    int i0 = ((t0 - 1) % 13 + 13) % 13;
    int i1 = ((t1 - 1) % 13 + 13) % 13;
    if (!((i0 == 12 && i1 == 0) || (i0 == 0 && i1 == 12))) {
        run_generic(x, par, out, g, m, staind, i0, i1);
        return;
    }

    // ---- chain-constant parameters ----
    HC c;
    {
        const float* pb = par + ((size_t)staind*NG + (size_t)g)*13u*MUc + m;
        float cp[13];
        #pragma unroll
        for (int p = 0; p < 13; p++)
            cp[p] = fmaf(pb[p*MUc], (UBc[p]-LBc[p]), LBc[p]);
        c.FC = cp[1]; c.K0 = cp[2]; c.K1 = cp[3]; c.K2 = cp[4];
        c.PERCc = cp[6]; c.UZL = cp[7]; c.TT = cp[8]; c.negCWH = -cp[11];
        c.CFMAX = cp[9];
        c.negCFMAXTT = -cp[9]*cp[8];
        c.negCFR = -cp[10];
        c.neglgFC   = -fast_lg2(cp[1]);
        c.neglgLPFC = -fast_lg2(cp[5]*cp[1]);
    }

    float SP=0.001f, MW=0.001f, SM=0.001f, SUZ=0.001f, SLZ=0.001f;
    const unsigned FULL = 0xffffffffu;
    const bool hi4 = (m & 4) != 0, hi2 = (m & 2) != 0, h1 = (m & 1) != 0;

    const float4* pB  = g_B  + tid;     // advance NCHAIN per batch
    const float4* pBT = g_BT + tid;
    const float4* pe  = g_PTEL + g;     // advance 4*NG per batch

    // pipeline: B/BT prefetch distance 2; PTEL distance 1 (L1-shared in block)
    float4 cB  = pB [0],       cBT  = pBT[0];
    float4 n1B = pB [NCHAIN],  n1BT = pBT[NCHAIN];
    float4 e0 = pe[0], e1 = pe[NG], e2 = pe[2*NG], e3 = pe[3*NG];

    for (int b = 0; b < TCHUNK; b++) {
        float4 n2B, n2BT, f0, f1, f2, f3;
        const bool pf2 = (b + 2 < TCHUNK);
        const bool pf1 = (b + 1 < TCHUNK);
        if (pf2) { n2B = pB[2*NCHAIN]; n2BT = pBT[2*NCHAIN]; }
        if (pf1) { f0 = pe[4*NG]; f1 = pe[5*NG]; f2 = pe[6*NG]; f3 = pe[7*NG]; }

        float q0 = hbv_step(SP,MW,SM,SUZ,SLZ,c, e0.x,e0.y,e0.z,e0.w, cB.x, cBT.x);
        float q1 = hbv_step(SP,MW,SM,SUZ,SLZ,c, e1.x,e1.y,e1.z,e1.w, cB.y, cBT.y);
        float q2 = hbv_step(SP,MW,SM,SUZ,SLZ,c, e2.x,e2.y,e2.z,e2.w, cB.z, cBT.z);
        float q3 = hbv_step(SP,MW,SM,SUZ,SLZ,c, e3.x,e3.y,e3.z,e3.w, cB.w, cBT.w);

        // reduce-scatter over 8-lane mu group: lane pair owns item 2*hi4+hi2
        float s1_0, s1_1;
        {
            float send0 = hi4 ? q0 : q2;
            float send1 = hi4 ? q1 : q3;
            float recv0 = __shfl_xor_sync(FULL, send0, 4);
            float recv1 = __shfl_xor_sync(FULL, send1, 4);
            s1_0 = (hi4 ? q2 : q0) + recv0;
            s1_1 = (hi4 ? q3 : q1) + recv1;
        }
        float s2;
        {
            float send = hi2 ? s1_0 : s1_1;
            float recv = __shfl_xor_sync(FULL, send, 2);
            s2 = (hi2 ? s1_1 : s1_0) + recv;
        }
        float tot = s2 + __shfl_xor_sync(FULL, s2, 1);
        int item = (hi4 ? 2 : 0) + (hi2 ? 1 : 0);
        int step = b*4 + item;
        if (!h1 && step < NS)
            out[(size_t)step*NG + g] = tot * 0.125f;

        // rotate pipeline
        cB = n1B; cBT = n1BT;
        if (pf2) { n1B = n2B; n1BT = n2BT; }
        if (pf1) { e0 = f0; e1 = f1; e2 = f2; e3 = f3; }
        pB += NCHAIN; pBT += NCHAIN; pe += 4*NG;
    }
}

extern "C" void kernel_launch(void* const* d_in, const int* in_sizes, int n_in,
                              void* d_out, int out_size)
{
    const float* x      = (const float*)d_in[0];   // (730, 1000, 3) f32
    const float* par    = (const float*)d_in[1];   // (730, 1000, 13, 8) f32
    const int*   staind = (const int*)d_in[2];     // scalar
    const int*   tdlst  = (const int*)d_in[3];     // (2,) int32
    int n_td = in_sizes[3];
    (void)n_in; (void)out_size;

    repack_par<<<(TCHUNK*NCHAIN + 255)/256, 256>>>(par);
    repack_x  <<<(NS*NG + 255)/256, 256>>>(x);
    hbv_main  <<<(NCHAIN + 255)/256, 256>>>(x, par, staind, tdlst, n_td, (float*)d_out);
}

// round 15
// speedup vs baseline: 2.0041x; 1.4384x over previous
#include <cuda_runtime.h>
#include <cstdint>
#include <cstddef>

#define NS   730
#define NG   1000
#define MUc  8
#define NCH  (NG*MUc)
#define BATCH 8
#define PRECSf 1e-05f
#define XS   (NG*3)
#define PS   (NG*13*MUc)

__constant__ float LBc[13] = {1.0f, 50.0f, 0.05f, 0.01f, 0.001f, 0.2f, 0.0f, 0.0f, -2.5f, 0.5f, 0.0f, 0.0f, 0.3f};
__constant__ float UBc[13] = {6.0f, 1000.0f, 0.9f, 0.5f, 0.2f, 1.0f, 10.0f, 100.0f, 2.5f, 10.0f, 0.1f, 0.2f, 5.0f};

__device__ __forceinline__ float fast_lg2(float a) {
    float r; asm("lg2.approx.f32 %0, %1;" : "=f"(r) : "f"(a)); return r;
}
__device__ __forceinline__ float fast_ex2(float a) {
    float r; asm("ex2.approx.f32 %0, %1;" : "=f"(r) : "f"(a)); return r;
}

// ============================================================================
// Specialized path: time-varying slots are exactly {12=BETAET, 0=BETA}.
// ============================================================================
__device__ __forceinline__ void run_spec(
    const float* __restrict__ x, const float* __restrict__ par,
    float* __restrict__ out, int g, int m, int staind,
    const float* __restrict__ ppBET, const float* __restrict__ ppB)
{
    float cp[13];
    {
        const float* pb = par + ((size_t)staind*NG + (size_t)g)*13u*MUc + m;
        #pragma unroll
        for (int p = 0; p < 13; p++)
            cp[p] = fmaf(pb[p*MUc], (UBc[p]-LBc[p]), LBc[p]);
    }
    const float FC=cp[1], K0=cp[2], K1=cp[3], K2=cp[4], LP=cp[5],
                PERCc=cp[6], UZL=cp[7], TT=cp[8], CFMAX=cp[9], CFR=cp[10], CWH=cp[11];
    const float neglgFC    = -fast_lg2(FC);
    const float neglgLPFC  = -fast_lg2(LP*FC);
    const float negCFMAXTT = -CFMAX*TT;
    const float negCFR     = -CFR;
    const float negCWH     = -CWH;
    const float dBET = UBc[12]-LBc[12], lbBET = LBc[12];
    const float dB   = UBc[0] -LBc[0],  lbB   = LBc[0];

    float SP=0.001f, MW=0.001f, SM=0.001f, SUZ=0.001f, SLZ=0.001f;
    const float invmu = 1.0f/(float)MUc;
    const unsigned FULL = 0xffffffffu;
    const bool hi4 = (m & 4) != 0, hi2 = (m & 2) != 0, hi1 = (m & 1) != 0;

    const float* xp = x + (size_t)g*3;
    float* outp = out + (size_t)m*NG + g;

    // current-batch raw buffers
    float cP[BATCH], cT[BATCH], cE[BATCH], cBT[BATCH], cB[BATCH];
    #pragma unroll
    for (int j = 0; j < BATCH; j++) {
        cP [j] = xp[j*XS + 0];
        cT [j] = xp[j*XS + 1];
        cE [j] = xp[j*XS + 2];
        cBT[j] = ppBET[j*PS];
        cB [j] = ppB  [j*PS];
    }

    // ---- phase-split batch ----
    auto do_batch = [&](const float* P, const float* T, const float* E,
                        const float* BTraw, const float* Braw, float* dst) {
        // Phase S: snow recurrence (SP/MW chain) + parameter transforms.
        float rt[BATCH], C1[BATCH], C2[BATCH], BB[BATCH], BT[BATCH];
        #pragma unroll
        for (int j = 0; j < BATCH; j++) {
            float BETA   = fmaf(Braw[j],  dB,   lbB);
            float BETAET = fmaf(BTraw[j], dBET, lbBET);
            BB[j] = BETA; BT[j] = BETAET;
            C1[j] = BETA   * neglgFC;
            C2[j] = BETAET * neglgLPFC;
            float m0 = fmaf(CFMAX, T[j], negCFMAXTT);
            float mm = fmaxf(m0, 0.0f);
            float rr = fmaxf(negCFR*m0, 0.0f);
            bool  wet = (T[j] >= TT);
            float rain = wet ? P[j] : 0.0f;
            float snow = wet ? 0.0f : P[j];
            SP += snow;
            float melt = fminf(mm, SP);
            MW += melt; SP -= melt;
            float refr = fminf(rr, MW);
            SP += refr; MW -= refr;
            float tosoil = fmaxf(fmaf(negCWH, SP, MW), 0.0f);
            MW -= tosoil;
            rt[j] = rain + tosoil;
        }
        // Phase M: the SM transcendental chain (pure).
        float rech[BATCH], exc[BATCH];
        #pragma unroll
        for (int j = 0; j < BATCH; j++) {
            float lgSM = fast_lg2(SM);
            float sw   = fast_ex2(fminf(fmaf(BB[j], lgSM, C1[j]), 0.0f));
            float recharge = rt[j] * sw;
            float smrt = SM + rt[j];
            float SM1  = smrt - recharge;
            float SM2  = fminf(SM1, FC);
            exc[j]  = SM1 - SM2;
            rech[j] = recharge;
            float lgSM2 = fast_lg2(SM2);
            float ef    = fminf(fast_ex2(fmaf(BT[j], lgSM2, C2[j])), 1.0f);
            float ETact = fminf(SM2, E[j]*ef);
            SM = fmaxf(SM2 - ETact, PRECSf);
        }
        // Phase R: routing recurrence (SUZ/SLZ chain).
        float q[BATCH];
        #pragma unroll
        for (int j = 0; j < BATCH; j++) {
            SUZ += rech[j] + exc[j];
            float PERC = fminf(SUZ, PERCc);
            SUZ -= PERC;
            float Q0 = K0 * fmaxf(SUZ - UZL, 0.0f);
            SUZ -= Q0;
            float Q1 = K1 * SUZ;
            SUZ -= Q1;
            SLZ += PERC;
            float Q2 = K2 * SLZ;
            SLZ -= Q2;
            q[j] = Q0 + Q1 + Q2;
        }
        // reduce-scatter: lane m owns step base+m
        float s1[4];
        #pragma unroll
        for (int e = 0; e < 4; e++) {
            float send = hi4 ? q[e] : q[e+4];
            float recv = __shfl_xor_sync(FULL, send, 4);
            s1[e] = (hi4 ? q[e+4] : q[e]) + recv;
        }
        float s2[2];
        #pragma unroll
        for (int e = 0; e < 2; e++) {
            float send = hi2 ? s1[e] : s1[e+2];
            float recv = __shfl_xor_sync(FULL, send, 2);
            s2[e] = (hi2 ? s1[e+2] : s1[e]) + recv;
        }
        float send = hi1 ? s2[0] : s2[1];
        float recv = __shfl_xor_sync(FULL, send, 1);
        float tot  = (hi1 ? s2[1] : s2[0]) + recv;
        *dst = tot * invmu;
    };

    // 91 full batches (b=0..90, steps 0..727); prefetch b+1 when b<90.
    const float* xq = xp    + BATCH*XS;
    const float* qT = ppBET + BATCH*PS;
    const float* qB = ppB   + BATCH*PS;
    for (int b = 0; b <= 90; b++) {
        const bool pf = (b < 90);
        float nP[BATCH], nT[BATCH], nE[BATCH], nBT[BATCH], nB[BATCH];
        if (pf) {
            #pragma unroll
            for (int j = 0; j < BATCH; j++) {
                nP [j] = xq[j*XS + 0];
                nT [j] = xq[j*XS + 1];
                nE [j] = xq[j*XS + 2];
                nBT[j] = qT[j*PS];
                nB [j] = qB[j*PS];
            }
        }
        do_batch(cP, cT, cE, cBT, cB, outp);
        outp += BATCH*NG;
        if (pf) {
            xq += BATCH*XS; qT += BATCH*PS; qB += BATCH*PS;
            #pragma unroll
            for (int j = 0; j < BATCH; j++) {
                cP[j]=nP[j]; cT[j]=nT[j]; cE[j]=nE[j]; cBT[j]=nBT[j]; cB[j]=nB[j];
            }
        }
    }

    // tail: steps 728, 729 (serial, simple)
    #pragma unroll
    for (int t = 91*BATCH; t < NS; t++) {
        float P_ = xp[(long)t*XS + 0];
        float T_ = xp[(long)t*XS + 1];
        float E_ = xp[(long)t*XS + 2];
        float BETAET = fmaf(ppBET[(long)t*PS], dBET, lbBET);
        float BETA   = fmaf(ppB  [(long)t*PS], dB,   lbB);
        float m0 = fmaf(CFMAX, T_, negCFMAXTT);
        float mm = fmaxf(m0, 0.0f);
        float rr = fmaxf(negCFR*m0, 0.0f);
        bool  wet = (T_ >= TT);
        float rain = wet ? P_ : 0.0f;
        float snow = wet ? 0.0f : P_;
        SP += snow;
        float melt = fminf(mm, SP);
        MW += melt; SP -= melt;
        float refr = fminf(rr, MW);
        SP += refr; MW -= refr;
        float tosoil = fmaxf(fmaf(negCWH, SP, MW), 0.0f);
        MW -= tosoil;
        float rt = rain + tosoil;
        float lgSM = fast_lg2(SM);
        float sw   = fast_ex2(fminf(fmaf(BETA, lgSM, BETA*neglgFC), 0.0f));
        float recharge = rt * sw;
        float SM1 = (SM + rt) - recharge;
        float SM2 = fminf(SM1, FC);
        float excess = SM1 - SM2;
        float lgSM2 = fast_lg2(SM2);
        float ef    = fminf(fast_ex2(fmaf(BETAET, lgSM2, BETAET*neglgLPFC)), 1.0f);
        float ETact = fminf(SM2, E_*ef);
        SM = fmaxf(SM2 - ETact, PRECSf);
        SUZ += recharge + excess;
        float PERC = fminf(SUZ, PERCc);
        SUZ -= PERC;
        float Q0 = K0 * fmaxf(SUZ - UZL, 0.0f);
        SUZ -= Q0;
        float Q1 = K1 * SUZ;
        SUZ -= Q1;
        SLZ += PERC;
        float Q2 = K2 * SLZ;
        SLZ -= Q2;
        float qv = Q0 + Q1 + Q2;
        qv += __shfl_xor_sync(FULL, qv, 1);
        qv += __shfl_xor_sync(FULL, qv, 2);
        qv += __shfl_xor_sync(FULL, qv, 4);
        if (m == 0) out[(size_t)t*NG + g] = qv * invmu;
    }
}

// ============================================================================
// Generic fallback (any i0/i1).
// ============================================================================
__device__ void run_generic(
    const float* __restrict__ x, const float* __restrict__ par,
    float* __restrict__ out, int g, int m, int staind, int i0, int i1)
{
    float cp[13];
    {
        const float* pb = par + ((size_t)staind*NG + (size_t)g)*13u*MUc + m;
        #pragma unroll
        for (int p = 0; p < 13; p++)
            cp[p] = fmaf(pb[p*MUc], (UBc[p]-LBc[p]), LBc[p]);
    }
    const float lb0 = LBc[i0], d0 = UBc[i0]-LBc[i0];
    const float lb1 = LBc[i1], d1 = UBc[i1]-LBc[i1];
    const float* xp  = x   + (size_t)g*3;
    const float* pp0 = par + ((size_t)g*13 + (size_t)i0)*MUc + m;
    const float* pp1 = par + ((size_t)g*13 + (size_t)i1)*MUc + m;

    float SP=0.001f, MW=0.001f, SM=0.001f, SUZ=0.001f, SLZ=0.001f;
    const unsigned FULL = 0xffffffffu;

    for (int t = 0; t < NS; t++) {
        float P_ = xp[(long)t*XS + 0];
        float T_ = xp[(long)t*XS + 1];
        float E_ = xp[(long)t*XS + 2];
        float v0 = fmaf(pp0[(long)t*PS], d0, lb0);
        float v1 = fmaf(pp1[(long)t*PS], d1, lb1);
        float pr[13];
        #pragma unroll
        for (int p = 0; p < 13; p++) {
            float v = cp[p];
            if (p == i0) v = v0;
            if (p == i1) v = v1;
            pr[p] = v;
        }
        float BETA=pr[0], FC=pr[1], K0=pr[2], K1=pr[3], K2=pr[4], LP=pr[5],
              PERCc=pr[6], UZL=pr[7], TT=pr[8], CFMAX=pr[9], CFR=pr[10],
              CWH=pr[11], BETAET=pr[12];
        float rain = (T_ >= TT) ? P_ : 0.0f;
        float snow = P_ - rain;
        SP += snow;
        float melt = fminf(fmaxf(CFMAX*(T_-TT), 0.0f), SP);
        MW += melt; SP -= melt;
        float refr = fminf(fmaxf(CFR*CFMAX*(TT-T_), 0.0f), MW);
        SP += refr; MW -= refr;
        float tosoil = fmaxf(MW - CWH*SP, 0.0f);
        MW -= tosoil;
        float sw = fminf(fast_ex2(BETA*(fast_lg2(SM) - fast_lg2(FC))), 1.0f);
        float rt = rain + tosoil;
        float recharge = rt * sw;
        float SM1 = SM + rt - recharge;
        float excess = fmaxf(SM1 - FC, 0.0f);
        float SM2 = SM1 - excess;
        float ef = fminf(fast_ex2(BETAET*(fast_lg2(SM2) - fast_lg2(LP*FC))), 1.0f);
        float ETact = fminf(SM2, E_*ef);
        SM = fmaxf(SM2 - ETact, PRECSf);
        SUZ += recharge + excess;
        float PERC = fminf(SUZ, PERCc);
        SUZ -= PERC;
        float Q0 = K0 * fmaxf(SUZ - UZL, 0.0f);
        SUZ -= Q0;
        float Q1 = K1 * SUZ;
        SUZ -= Q1;
        SLZ += PERC;
        float Q2 = K2 * SLZ;
        SLZ -= Q2;
        float qv = Q0 + Q1 + Q2;
        qv += __shfl_xor_sync(FULL, qv, 1);
        qv += __shfl_xor_sync(FULL, qv, 2);
        qv += __shfl_xor_sync(FULL, qv, 4);
        if (m == 0) out[(size_t)t*NG + g] = qv * 0.125f;
    }
}

__global__ void __launch_bounds__(64, 1)
hbv_kernel(const float* __restrict__ x, const float* __restrict__ par,
           const int* __restrict__ staind_p, const int* __restrict__ tdlst_p,
           int n_td, float* __restrict__ out)
{
    int tid = blockIdx.x * 64 + threadIdx.x;   // 8000 threads exactly
    int g = tid >> 3;
    int m = tid & 7;
    int staind = staind_p[0];
    int t0 = tdlst_p[0];
    int t1 = (n_td > 1) ? tdlst_p[1] : t0;
    int i0 = ((t0 - 1) % 13 + 13) % 13;
    int i1 = ((t1 - 1) % 13 + 13) % 13;

    const long PS_base = (size_t)g*13*MUc + m;
    if ((i0 == 12 && i1 == 0) || (i0 == 0 && i1 == 12)) {
        run_spec(x, par, out, g, m, staind,
                 par + PS_base + 12*MUc, par + PS_base + 0*MUc);
    } else {
        run_generic(x, par, out, g, m, staind, i0, i1);
    }
}

extern "C" void kernel_launch(void* const* d_in, const int* in_sizes, int n_in,
                              void* d_out, int out_size)
{
    const float* x      = (const float*)d_in[0];   // (730, 1000, 3) f32
    const float* par    = (const float*)d_in[1];   // (730, 1000, 13, 8) f32
    const int*   staind = (const int*)d_in[2];     // scalar
    const int*   tdlst  = (const int*)d_in[3];     // (2,) int32
    int n_td = in_sizes[3];
    (void)n_in; (void)out_size;
    hbv_kernel<<<NCH/64, 64>>>(x, par, staind, tdlst, n_td, (float*)d_out);
}